// round 3
// baseline (speedup 1.0000x reference)
#include <cuda_runtime.h>

#define NA 12
#define NT 4096
#define NN (NT*NA)
#define DIM 3
#define NV 4
#define HID 64
#define INF 32
#define EPE 132            // edges per env (12*11)
#define THREADS 512
#define EPB 27             // envs per block -> GRID=152 = 1 wave on GB300 (152 SMs)
#define GRID ((NT + EPB - 1) / EPB)   // 152
#define TST 68             // padded row stride for t/m (kills stride-64 bank conflicts)

// global scratch (static device arrays — no allocation)
__device__ float g_h[NN * HID];        // 12.6 MB
__device__ float g_x[NN * DIM * NV];   // 2.4 MB

struct Smem {
    // per-layer weights (reloaded each layer)
    float We1[EPE * HID];      // 132x64 : rows 0..63 -> hi part, 64..127 -> hj part, 128..131 -> radial
    float W2[HID * HID];       // We2 (also reused for W_embed during embed phase)
    float Wxw[HID * NV];
    float Wh1w[2 * HID * HID];
    float Wh2w[HID * HID];
    float b1[HID], b2[HID], bh1v[HID], bh2v[HID], bxb[NV];
    int   ei[EPE], ej[EPE];
    // per-env state / buffers
    float h[NA * HID];
    float a[NA * HID];
    float bb[NA * HID];
    float t[EPE * TST];
    float m[EPE * TST];
    float dif[EPE * DIM * NV];
    float rad[EPE * NV];
    float wc[EPE * NV];
    float agg[NA * HID];
    float u[NA * HID];
    float x[NA * DIM * NV];
};

__device__ __forceinline__ float siluf(float z) { return z / (1.0f + __expf(-z)); }

__device__ __forceinline__ void copy4(float* dst, const float* src, int n, int tid) {
    const float4* s4 = (const float4*)src;
    float4* d4 = (float4*)dst;
    for (int o = tid; o < (n >> 2); o += THREADS) d4[o] = s4[o];
}

__global__ void __launch_bounds__(THREADS, 1) egnn_kernel(
    const float* __restrict__ h0, const float* __restrict__ x0,
    const float* __restrict__ W_embed, const float* __restrict__ b_embed,
    const float* __restrict__ We1p, const float* __restrict__ be1,
    const float* __restrict__ We2p, const float* __restrict__ be2,
    const float* __restrict__ Wxp, const float* __restrict__ bxp,
    const float* __restrict__ Wh1p, const float* __restrict__ bh1p,
    const float* __restrict__ Wh2p, const float* __restrict__ bh2p,
    const float* __restrict__ w_act, const float* __restrict__ log_std,
    float* __restrict__ out)
{
    extern __shared__ float sraw[];
    Smem* S = reinterpret_cast<Smem*>(sraw);
    const int tid = threadIdx.x;
    const int env0 = blockIdx.x * EPB;
    const int env1 = min(NT, env0 + EPB);
    if (env0 >= env1) return;

    // edge index tables
    if (tid < EPE) {
        int i = tid / 11, jj = tid - i * 11;
        S->ei[tid] = i;
        S->ej[tid] = jj + (jj >= i ? 1 : 0);
    }

    // ---------------- embed phase: h = h0 @ W_embed + b_embed ----------------
    copy4(S->W2, W_embed, INF * HID, tid);
    if (tid < HID) S->b2[tid] = b_embed[tid];
    __syncthreads();

    for (int env = env0; env < env1; env++) {
        const float* hsrc = h0 + (size_t)env * NA * INF;
        float* hdst = g_h + (size_t)env * NA * HID;
        for (int o = tid; o < NA * HID; o += THREADS) {
            int node = o >> 6, k = o & 63;
            const float* hr = hsrc + node * INF;
            float acc = S->b2[k];
            #pragma unroll
            for (int c = 0; c < INF; c++) acc += hr[c] * S->W2[c * HID + k];
            hdst[o] = acc;
        }
    }
    __syncthreads();

    const float wa0 = w_act[0], wa1 = w_act[1], wa2 = w_act[2], wa3 = w_act[3];
    float lp[DIM];
    #pragma unroll
    for (int d = 0; d < DIM; d++) lp[d] = -log_std[d] - 0.91893853320467274178f; // -0.5*log(2*pi)

    // ---------------- layer loop ----------------
    for (int l = 0; l < 2; l++) {
        // load layer weights into shared
        copy4(S->We1, We1p + (size_t)l * EPE * HID, EPE * HID, tid);
        copy4(S->W2, We2p + (size_t)l * HID * HID, HID * HID, tid);
        copy4(S->Wxw, Wxp + (size_t)l * HID * NV, HID * NV, tid);
        copy4(S->Wh1w, Wh1p + (size_t)l * 2 * HID * HID, 2 * HID * HID, tid);
        copy4(S->Wh2w, Wh2p + (size_t)l * HID * HID, HID * HID, tid);
        if (tid < HID) {
            S->b1[tid]  = be1[l * HID + tid];
            S->b2[tid]  = be2[l * HID + tid];
            S->bh1v[tid] = bh1p[l * HID + tid];
            S->bh2v[tid] = bh2p[l * HID + tid];
        }
        if (tid < NV) S->bxb[tid] = bxp[l * NV + tid];
        __syncthreads();

        const bool last = (l == 1);

        for (int env = env0; env < env1; env++) {
            // ---- phase 1: load state ----
            {
                const float4* gh4 = (const float4*)(g_h + (size_t)env * NA * HID);
                float4* sh4 = (float4*)S->h;
                for (int o = tid; o < (NA * HID) >> 2; o += THREADS) sh4[o] = gh4[o];
                const float* gx = (l == 0) ? (x0 + (size_t)env * NA * 12)
                                           : (g_x + (size_t)env * NA * 12);
                if (tid < NA * 12) S->x[tid] = gx[tid];
            }
            __syncthreads();

            // ---- phase 2: a/b node projections (384 threads) + diff + radial ----
            if (tid < 2 * NA * 16) {
                int part = (tid >= NA * 16);               // 0 -> a (hi proj), 1 -> bb (hj proj)
                int id = tid - part * NA * 16;
                int node = id >> 4, kq = id & 15, k0 = kq * 4;
                const float* Wbase = &S->We1[part * HID * HID];
                float f0 = 0.f, f1 = 0.f, f2 = 0.f, f3 = 0.f;
                const float* hrow = &S->h[node * HID];
                #pragma unroll 8
                for (int c = 0; c < HID; c++) {
                    float hv = hrow[c];
                    float4 wa = *(const float4*)&Wbase[c * HID + k0];
                    f0 += hv * wa.x; f1 += hv * wa.y; f2 += hv * wa.z; f3 += hv * wa.w;
                }
                float* dst = part ? &S->bb[node * HID + k0] : &S->a[node * HID + k0];
                *(float4*)dst = make_float4(f0, f1, f2, f3);
            }
            for (int o = tid; o < EPE * 12; o += THREADS) {
                int e = o / 12, dv = o - e * 12;
                S->dif[o] = S->x[S->ei[e] * 12 + dv] - S->x[S->ej[e] * 12 + dv];
            }
            for (int o = tid; o < EPE * NV; o += THREADS) {
                int e = o >> 2, v = o & 3;
                int i = S->ei[e] * 12, j = S->ej[e] * 12;
                float d0 = S->x[i + v]     - S->x[j + v];
                float d1 = S->x[i + 4 + v] - S->x[j + 4 + v];
                float d2 = S->x[i + 8 + v] - S->x[j + 8 + v];
                S->rad[o] = d0 * d0 + d1 * d1 + d2 * d2;
            }
            __syncthreads();

            // ---- phase 3: t = silu(a[i] + b[j] + radial @ We1r + be1) ----
            {
                const int kq = tid & 7, es = tid >> 3, k0 = kq * 4;
                float4 B0 = *(const float4*)&S->b1[k0];
                float4 B1 = *(const float4*)&S->b1[32 + k0];
                for (int e = es; e < EPE; e += 64) {
                    int i = S->ei[e], j = S->ej[e];
                    float4 a0 = *(const float4*)&S->a[i * HID + k0];
                    float4 a1 = *(const float4*)&S->a[i * HID + 32 + k0];
                    float4 c0 = *(const float4*)&S->bb[j * HID + k0];
                    float4 c1 = *(const float4*)&S->bb[j * HID + 32 + k0];
                    float z0=a0.x+c0.x+B0.x, z1=a0.y+c0.y+B0.y, z2=a0.z+c0.z+B0.z, z3=a0.w+c0.w+B0.w;
                    float z4=a1.x+c1.x+B1.x, z5=a1.y+c1.y+B1.y, z6=a1.z+c1.z+B1.z, z7=a1.w+c1.w+B1.w;
                    #pragma unroll
                    for (int v = 0; v < NV; v++) {
                        float rv = S->rad[e * 4 + v];
                        const float* wr = &S->We1[(128 + v) * HID];
                        float4 w0 = *(const float4*)&wr[k0];
                        float4 w1 = *(const float4*)&wr[32 + k0];
                        z0 += rv * w0.x; z1 += rv * w0.y; z2 += rv * w0.z; z3 += rv * w0.w;
                        z4 += rv * w1.x; z5 += rv * w1.y; z6 += rv * w1.z; z7 += rv * w1.w;
                    }
                    *(float4*)&S->t[e * TST + k0]      = make_float4(siluf(z0), siluf(z1), siluf(z2), siluf(z3));
                    *(float4*)&S->t[e * TST + 32 + k0] = make_float4(siluf(z4), siluf(z5), siluf(z6), siluf(z7));
                }
            }
            __syncthreads();

            // ---- phase 4: m = silu(t @ We2 + be2)   (dominant matmul) ----
            {
                const int kq = tid & 7, es = tid >> 3, k0 = kq * 4;
                for (int e = es; e < EPE; e += 64) {
                    float4 A0 = *(const float4*)&S->b2[k0];
                    float4 A1 = *(const float4*)&S->b2[32 + k0];
                    float q0=A0.x,q1=A0.y,q2=A0.z,q3=A0.w,q4=A1.x,q5=A1.y,q6=A1.z,q7=A1.w;
                    const float* trow = &S->t[e * TST];
                    #pragma unroll 16
                    for (int c = 0; c < HID; c++) {
                        float tc = trow[c];
                        float4 w0 = *(const float4*)&S->W2[c * HID + k0];
                        float4 w1 = *(const float4*)&S->W2[c * HID + 32 + k0];
                        q0 += tc * w0.x; q1 += tc * w0.y; q2 += tc * w0.z; q3 += tc * w0.w;
                        q4 += tc * w1.x; q5 += tc * w1.y; q6 += tc * w1.z; q7 += tc * w1.w;
                    }
                    *(float4*)&S->m[e * TST + k0]      = make_float4(siluf(q0), siluf(q1), siluf(q2), siluf(q3));
                    *(float4*)&S->m[e * TST + 32 + k0] = make_float4(siluf(q4), siluf(q5), siluf(q6), siluf(q7));
                }
            }
            __syncthreads();

            // ---- phase 5: agg (if not last) + wc (warp-cooperative) ----
            if (!last) {
                for (int o = tid; o < NA * HID; o += THREADS) {
                    int i = o >> 6, k = o & 63;
                    float acc = 0.f;
                    #pragma unroll
                    for (int jj = 0; jj < 11; jj++) acc += S->m[(i * 11 + jj) * TST + k];
                    S->agg[o] = acc;
                }
            }
            {
                int warp = tid >> 5, lane = tid & 31;
                float4 wx0 = *(const float4*)&S->Wxw[lane * 4];
                float4 wx1 = *(const float4*)&S->Wxw[(32 + lane) * 4];
                for (int e = warp; e < EPE; e += 16) {
                    float m0 = S->m[e * TST + lane];
                    float m1 = S->m[e * TST + 32 + lane];
                    float p0 = m0 * wx0.x + m1 * wx1.x;
                    float p1 = m0 * wx0.y + m1 * wx1.y;
                    float p2 = m0 * wx0.z + m1 * wx1.z;
                    float p3 = m0 * wx0.w + m1 * wx1.w;
                    #pragma unroll
                    for (int off = 16; off; off >>= 1) {
                        p0 += __shfl_xor_sync(0xffffffffu, p0, off);
                        p1 += __shfl_xor_sync(0xffffffffu, p1, off);
                        p2 += __shfl_xor_sync(0xffffffffu, p2, off);
                        p3 += __shfl_xor_sync(0xffffffffu, p3, off);
                    }
                    if (lane == 0) {
                        S->wc[e * 4 + 0] = p0 + S->bxb[0];
                        S->wc[e * 4 + 1] = p1 + S->bxb[1];
                        S->wc[e * 4 + 2] = p2 + S->bxb[2];
                        S->wc[e * 4 + 3] = p3 + S->bxb[3];
                    }
                }
            }
            __syncthreads();

            // ---- phase 6: x update (+writeback) and u = silu([h,agg]@Wh1+bh1) ----
            if (tid < NA * 12) {
                int o = tid;
                int i = o / 12, dv = o - i * 12, v = dv & 3;
                float acc = 0.f;
                #pragma unroll
                for (int jj = 0; jj < 11; jj++) {
                    int e = i * 11 + jj;
                    acc += S->dif[e * 12 + dv] * S->wc[e * 4 + v];
                }
                float nx = S->x[o] + acc * (1.0f / 11.0f);
                S->x[o] = nx;
                if (!last) g_x[(size_t)env * NA * 12 + o] = nx;
            }
            if (!last && tid >= 256 && tid < 256 + NA * 16) {
                int id = tid - 256;
                int node = id >> 4, kq = id & 15, k0 = kq * 4;
                float4 b4 = *(const float4*)&S->bh1v[k0];
                float u0 = b4.x, u1 = b4.y, u2 = b4.z, u3 = b4.w;
                const float* hrow = &S->h[node * HID];
                const float* arow = &S->agg[node * HID];
                #pragma unroll 8
                for (int c = 0; c < HID; c++) {
                    float hv = hrow[c], av = arow[c];
                    float4 w1 = *(const float4*)&S->Wh1w[c * HID + k0];
                    float4 w2 = *(const float4*)&S->Wh1w[(HID + c) * HID + k0];
                    u0 += hv * w1.x + av * w2.x;
                    u1 += hv * w1.y + av * w2.y;
                    u2 += hv * w1.z + av * w2.z;
                    u3 += hv * w1.w + av * w2.w;
                }
                *(float4*)&S->u[node * HID + k0] =
                    make_float4(siluf(u0), siluf(u1), siluf(u2), siluf(u3));
            }
            __syncthreads();

            // ---- phase 7: h update + writeback, or final output ----
            if (!last) {
                if (tid < NA * 16) {
                    int node = tid >> 4, kq = tid & 15, k0 = kq * 4;
                    float4 b4 = *(const float4*)&S->bh2v[k0];
                    float c0 = b4.x, c1 = b4.y, c2 = b4.z, c3 = b4.w;
                    const float* urow = &S->u[node * HID];
                    #pragma unroll 8
                    for (int c = 0; c < HID; c++) {
                        float uv = urow[c];
                        float4 w = *(const float4*)&S->Wh2w[c * HID + k0];
                        c0 += uv * w.x; c1 += uv * w.y; c2 += uv * w.z; c3 += uv * w.w;
                    }
                    float4 hold = *(const float4*)&S->h[node * HID + k0];
                    float4 res = make_float4(hold.x + c0, hold.y + c1, hold.z + c2, hold.w + c3);
                    *(float4*)&g_h[(size_t)env * NA * HID + node * HID + k0] = res;
                }
            } else {
                if (tid < NA * DIM) {
                    int o = tid;
                    int i = o / 3, d = o - i * 3;
                    const float* xr = &S->x[i * 12 + d * 4];
                    float mu = xr[0] * wa0 + xr[1] * wa1 + xr[2] * wa2 + xr[3] * wa3;
                    out[(size_t)env * NA * DIM + o] = mu;
                    out[(size_t)NN * DIM + (size_t)env * NA * DIM + o] = lp[d];
                }
            }
            __syncthreads();
        }
        __syncthreads();
    }
}

extern "C" void kernel_launch(void* const* d_in, const int* in_sizes, int n_in,
                              void* d_out, int out_size) {
    (void)in_sizes; (void)n_in; (void)out_size;
    const float* h0      = (const float*)d_in[0];
    const float* x0      = (const float*)d_in[1];
    const float* W_embed = (const float*)d_in[2];
    const float* b_embed = (const float*)d_in[3];
    const float* We1     = (const float*)d_in[4];
    const float* be1     = (const float*)d_in[5];
    const float* We2     = (const float*)d_in[6];
    const float* be2     = (const float*)d_in[7];
    const float* Wx      = (const float*)d_in[8];
    const float* bx      = (const float*)d_in[9];
    const float* Wh1     = (const float*)d_in[10];
    const float* bh1     = (const float*)d_in[11];
    const float* Wh2     = (const float*)d_in[12];
    const float* bh2     = (const float*)d_in[13];
    const float* w_act   = (const float*)d_in[14];
    const float* log_std = (const float*)d_in[15];
    float* out = (float*)d_out;

    size_t smem = sizeof(Smem);
    cudaFuncSetAttribute(egnn_kernel, cudaFuncAttributeMaxDynamicSharedMemorySize, (int)smem);
    egnn_kernel<<<GRID, THREADS, smem>>>(h0, x0, W_embed, b_embed, We1, be1, We2, be2,
                                         Wx, bx, Wh1, bh1, Wh2, bh2, w_act, log_std, out);
}

// round 16
// speedup vs baseline: 1.7621x; 1.7621x over previous
#include <cuda_runtime.h>

#define NA 12
#define NT 4096
#define NN (NT*NA)
#define DIM 3
#define NV 4
#define HID 64
#define INF 32
#define EPE 132            // edges per env (12*11)
#define THREADS 512
#define EPB 27             // envs per block -> GRID=152 = 1 wave on GB300 (152 SMs)
#define GRID ((NT + EPB - 1) / EPB)   // 152
#define TST 68             // padded row stride for t/m
#define HST 68             // padded row stride for h/agg/u (bank-conflict-free float4 row loads)

// global scratch (static device arrays — no allocation)
__device__ float g_h[NN * HID];        // 12.6 MB
__device__ float g_x[NN * DIM * NV];   // 2.4 MB

struct Smem {
    float We1[EPE * HID];      // rows 0..63 -> hi proj, 64..127 -> hj proj, 128..131 -> radial
    float W2[HID * HID];       // We2 (reused for W_embed during embed phase)
    float Wxw[HID * NV];
    float Wh1w[2 * HID * HID];
    float Wh2w[HID * HID];
    float b1[HID], b2[HID], bh1v[HID], bh2v[HID], bxb[NV];
    int   ei[EPE], ej[EPE];
    float h[NA * HST];
    float a[NA * HID];
    float bb[NA * HID];
    float t[EPE * TST];
    float m[EPE * TST];
    float dif[EPE * DIM * NV];
    float rad[EPE * NV];
    float wc[EPE * NV];
    float agg[NA * HST];
    float u[NA * HST];
    float x[NA * DIM * NV];
};

__device__ __forceinline__ float siluf(float z) { return z / (1.0f + __expf(-z)); }

__device__ __forceinline__ void copy4(float* dst, const float* src, int n, int tid) {
    const float4* s4 = (const float4*)src;
    float4* d4 = (float4*)dst;
    for (int o = tid; o < (n >> 2); o += THREADS) d4[o] = s4[o];
}

__global__ void __launch_bounds__(THREADS, 1) egnn_kernel(
    const float* __restrict__ h0, const float* __restrict__ x0,
    const float* __restrict__ W_embed, const float* __restrict__ b_embed,
    const float* __restrict__ We1p, const float* __restrict__ be1,
    const float* __restrict__ We2p, const float* __restrict__ be2,
    const float* __restrict__ Wxp, const float* __restrict__ bxp,
    const float* __restrict__ Wh1p, const float* __restrict__ bh1p,
    const float* __restrict__ Wh2p, const float* __restrict__ bh2p,
    const float* __restrict__ w_act, const float* __restrict__ log_std,
    float* __restrict__ out)
{
    extern __shared__ float sraw[];
    Smem* S = reinterpret_cast<Smem*>(sraw);
    const int tid = threadIdx.x;
    const int env0 = blockIdx.x * EPB;
    const int env1 = min(NT, env0 + EPB);
    if (env0 >= env1) return;

    if (tid < EPE) {
        int i = tid / 11, jj = tid - i * 11;
        S->ei[tid] = i;
        S->ej[tid] = jj + (jj >= i ? 1 : 0);
    }

    // ---------------- embed phase: h = h0 @ W_embed + b_embed ----------------
    copy4(S->W2, W_embed, INF * HID, tid);
    if (tid < HID) S->b2[tid] = b_embed[tid];
    __syncthreads();

    for (int env = env0; env < env1; env++) {
        const float* hsrc = h0 + (size_t)env * NA * INF;
        float* hdst = g_h + (size_t)env * NA * HID;
        for (int o = tid; o < NA * HID; o += THREADS) {
            int node = o >> 6, k = o & 63;
            const float* hr = hsrc + node * INF;
            float acc = S->b2[k];
            #pragma unroll
            for (int c = 0; c < INF; c++) acc += hr[c] * S->W2[c * HID + k];
            hdst[o] = acc;
        }
    }
    __syncthreads();

    const float wa0 = w_act[0], wa1 = w_act[1], wa2 = w_act[2], wa3 = w_act[3];
    float lp[DIM];
    #pragma unroll
    for (int d = 0; d < DIM; d++) lp[d] = -log_std[d] - 0.91893853320467274178f;

    // ---------------- layer loop ----------------
    for (int l = 0; l < 2; l++) {
        copy4(S->We1, We1p + (size_t)l * EPE * HID, EPE * HID, tid);
        copy4(S->W2, We2p + (size_t)l * HID * HID, HID * HID, tid);
        copy4(S->Wxw, Wxp + (size_t)l * HID * NV, HID * NV, tid);
        copy4(S->Wh1w, Wh1p + (size_t)l * 2 * HID * HID, 2 * HID * HID, tid);
        copy4(S->Wh2w, Wh2p + (size_t)l * HID * HID, HID * HID, tid);
        if (tid < HID) {
            S->b1[tid]   = be1[l * HID + tid];
            S->b2[tid]   = be2[l * HID + tid];
            S->bh1v[tid] = bh1p[l * HID + tid];
            S->bh2v[tid] = bh2p[l * HID + tid];
        }
        if (tid < NV) S->bxb[tid] = bxp[l * NV + tid];
        __syncthreads();

        const bool last = (l == 1);

        for (int env = env0; env < env1; env++) {
            // ---- phase 1: load state (h restrided to HST=68) ----
            {
                const float4* gh4 = (const float4*)(g_h + (size_t)env * NA * HID);
                float4* sh4 = (float4*)S->h;
                for (int o4 = tid; o4 < (NA * HID) >> 2; o4 += THREADS) {
                    int node = o4 >> 4, q = o4 & 15;
                    sh4[node * (HST >> 2) + q] = gh4[o4];
                }
                const float* gx = (l == 0) ? (x0 + (size_t)env * NA * 12)
                                           : (g_x + (size_t)env * NA * 12);
                if (tid < NA * 12) S->x[tid] = gx[tid];
            }
            __syncthreads();

            // ---- phase 2: a/bb node projections (192 thr, 8 out/thr) + diff + radial ----
            if (tid < 192) {
                int part = (tid >= 96);
                int r = tid - part * 96;
                int node = r >> 3, kq = r & 7, k0 = kq * 8;
                const float* Wb = &S->We1[part * HID * HID];
                const float* hrow = &S->h[node * HST];
                float q0=0,q1=0,q2=0,q3=0,q4=0,q5=0,q6=0,q7=0;
                #pragma unroll 2
                for (int c4 = 0; c4 < HID; c4 += 4) {
                    float4 h4 = *(const float4*)&hrow[c4];
                    float hv[4] = {h4.x, h4.y, h4.z, h4.w};
                    #pragma unroll
                    for (int cc = 0; cc < 4; cc++) {
                        float4 w0 = *(const float4*)&Wb[(c4 + cc) * HID + k0];
                        float4 w1 = *(const float4*)&Wb[(c4 + cc) * HID + k0 + 4];
                        q0 += hv[cc] * w0.x; q1 += hv[cc] * w0.y; q2 += hv[cc] * w0.z; q3 += hv[cc] * w0.w;
                        q4 += hv[cc] * w1.x; q5 += hv[cc] * w1.y; q6 += hv[cc] * w1.z; q7 += hv[cc] * w1.w;
                    }
                }
                float* dst = (part ? S->bb : S->a) + node * HID + k0;
                *(float4*)&dst[0] = make_float4(q0, q1, q2, q3);
                *(float4*)&dst[4] = make_float4(q4, q5, q6, q7);
            }
            for (int o = tid; o < EPE * 12; o += THREADS) {
                int e = o / 12, dv = o - e * 12;
                S->dif[o] = S->x[S->ei[e] * 12 + dv] - S->x[S->ej[e] * 12 + dv];
            }
            for (int o = tid; o < EPE * NV; o += THREADS) {
                int e = o >> 2, v = o & 3;
                int i = S->ei[e] * 12, j = S->ej[e] * 12;
                float d0 = S->x[i + v]     - S->x[j + v];
                float d1 = S->x[i + 4 + v] - S->x[j + 4 + v];
                float d2 = S->x[i + 8 + v] - S->x[j + 8 + v];
                S->rad[o] = d0 * d0 + d1 * d1 + d2 * d2;
            }
            __syncthreads();

            // ---- phase 3: t = silu(a[i] + bb[j] + radial @ We1r + be1) ----
            {
                const int kq = tid & 7, es = tid >> 3, k0 = kq * 4;
                float4 B0 = *(const float4*)&S->b1[k0];
                float4 B1 = *(const float4*)&S->b1[32 + k0];
                for (int e = es; e < EPE; e += 64) {
                    int i = S->ei[e], j = S->ej[e];
                    float4 a0 = *(const float4*)&S->a[i * HID + k0];
                    float4 a1 = *(const float4*)&S->a[i * HID + 32 + k0];
                    float4 c0 = *(const float4*)&S->bb[j * HID + k0];
                    float4 c1 = *(const float4*)&S->bb[j * HID + 32 + k0];
                    float4 r4 = *(const float4*)&S->rad[e * 4];
                    float rv[4] = {r4.x, r4.y, r4.z, r4.w};
                    float z0=a0.x+c0.x+B0.x, z1=a0.y+c0.y+B0.y, z2=a0.z+c0.z+B0.z, z3=a0.w+c0.w+B0.w;
                    float z4=a1.x+c1.x+B1.x, z5=a1.y+c1.y+B1.y, z6=a1.z+c1.z+B1.z, z7=a1.w+c1.w+B1.w;
                    #pragma unroll
                    for (int v = 0; v < NV; v++) {
                        const float* wr = &S->We1[(128 + v) * HID];
                        float4 w0 = *(const float4*)&wr[k0];
                        float4 w1 = *(const float4*)&wr[32 + k0];
                        z0 += rv[v] * w0.x; z1 += rv[v] * w0.y; z2 += rv[v] * w0.z; z3 += rv[v] * w0.w;
                        z4 += rv[v] * w1.x; z5 += rv[v] * w1.y; z6 += rv[v] * w1.z; z7 += rv[v] * w1.w;
                    }
                    *(float4*)&S->t[e * TST + k0]      = make_float4(siluf(z0), siluf(z1), siluf(z2), siluf(z3));
                    *(float4*)&S->t[e * TST + 32 + k0] = make_float4(siluf(z4), siluf(z5), siluf(z6), siluf(z7));
                }
            }
            __syncthreads();

            // ---- phase 4: m = silu(t @ We2 + be2) — 2 edges/thread, weights reused ----
            {
                const int kq = tid & 7, es = tid >> 3, k0 = kq * 4;
                float4 A0 = *(const float4*)&S->b2[k0];
                float4 A1 = *(const float4*)&S->b2[32 + k0];
                float p0=A0.x,p1=A0.y,p2=A0.z,p3=A0.w,p4=A1.x,p5=A1.y,p6=A1.z,p7=A1.w;
                float r0=A0.x,r1=A0.y,r2=A0.z,r3=A0.w,r4=A1.x,r5=A1.y,r6=A1.z,r7=A1.w;
                const float* t0 = &S->t[es * TST];
                const float* t1 = &S->t[(es + 64) * TST];
                #pragma unroll 2
                for (int c4 = 0; c4 < HID; c4 += 4) {
                    float4 ta4 = *(const float4*)&t0[c4];
                    float4 tb4 = *(const float4*)&t1[c4];
                    float ta[4] = {ta4.x, ta4.y, ta4.z, ta4.w};
                    float tb[4] = {tb4.x, tb4.y, tb4.z, tb4.w};
                    #pragma unroll
                    for (int cc = 0; cc < 4; cc++) {
                        float4 w0 = *(const float4*)&S->W2[(c4 + cc) * HID + k0];
                        float4 w1 = *(const float4*)&S->W2[(c4 + cc) * HID + 32 + k0];
                        p0 += ta[cc] * w0.x; p1 += ta[cc] * w0.y; p2 += ta[cc] * w0.z; p3 += ta[cc] * w0.w;
                        p4 += ta[cc] * w1.x; p5 += ta[cc] * w1.y; p6 += ta[cc] * w1.z; p7 += ta[cc] * w1.w;
                        r0 += tb[cc] * w0.x; r1 += tb[cc] * w0.y; r2 += tb[cc] * w0.z; r3 += tb[cc] * w0.w;
                        r4 += tb[cc] * w1.x; r5 += tb[cc] * w1.y; r6 += tb[cc] * w1.z; r7 += tb[cc] * w1.w;
                    }
                }
                *(float4*)&S->m[es * TST + k0]             = make_float4(siluf(p0), siluf(p1), siluf(p2), siluf(p3));
                *(float4*)&S->m[es * TST + 32 + k0]        = make_float4(siluf(p4), siluf(p5), siluf(p6), siluf(p7));
                *(float4*)&S->m[(es + 64) * TST + k0]      = make_float4(siluf(r0), siluf(r1), siluf(r2), siluf(r3));
                *(float4*)&S->m[(es + 64) * TST + 32 + k0] = make_float4(siluf(r4), siluf(r5), siluf(r6), siluf(r7));
                if (es >= 60) {  // tail: edges 128..131 (warp 15 only)
                    const int e2 = es + 68;
                    float s0=A0.x,s1=A0.y,s2=A0.z,s3=A0.w,s4=A1.x,s5=A1.y,s6=A1.z,s7=A1.w;
                    const float* t2 = &S->t[e2 * TST];
                    #pragma unroll 2
                    for (int c4 = 0; c4 < HID; c4 += 4) {
                        float4 tc4 = *(const float4*)&t2[c4];
                        float tc[4] = {tc4.x, tc4.y, tc4.z, tc4.w};
                        #pragma unroll
                        for (int cc = 0; cc < 4; cc++) {
                            float4 w0 = *(const float4*)&S->W2[(c4 + cc) * HID + k0];
                            float4 w1 = *(const float4*)&S->W2[(c4 + cc) * HID + 32 + k0];
                            s0 += tc[cc] * w0.x; s1 += tc[cc] * w0.y; s2 += tc[cc] * w0.z; s3 += tc[cc] * w0.w;
                            s4 += tc[cc] * w1.x; s5 += tc[cc] * w1.y; s6 += tc[cc] * w1.z; s7 += tc[cc] * w1.w;
                        }
                    }
                    *(float4*)&S->m[e2 * TST + k0]      = make_float4(siluf(s0), siluf(s1), siluf(s2), siluf(s3));
                    *(float4*)&S->m[e2 * TST + 32 + k0] = make_float4(siluf(s4), siluf(s5), siluf(s6), siluf(s7));
                }
            }
            __syncthreads();

            // ---- phase 5: agg (if not last) + wc (warp-cooperative) ----
            if (!last) {
                for (int o = tid; o < NA * HID; o += THREADS) {
                    int i = o >> 6, k = o & 63;
                    float acc = 0.f;
                    #pragma unroll
                    for (int jj = 0; jj < 11; jj++) acc += S->m[(i * 11 + jj) * TST + k];
                    S->agg[i * HST + k] = acc;
                }
            }
            {
                int warp = tid >> 5, lane = tid & 31;
                float4 wx0 = *(const float4*)&S->Wxw[lane * 4];
                float4 wx1 = *(const float4*)&S->Wxw[(32 + lane) * 4];
                for (int e = warp; e < EPE; e += 16) {
                    float m0 = S->m[e * TST + lane];
                    float m1 = S->m[e * TST + 32 + lane];
                    float p0 = m0 * wx0.x + m1 * wx1.x;
                    float p1 = m0 * wx0.y + m1 * wx1.y;
                    float p2 = m0 * wx0.z + m1 * wx1.z;
                    float p3 = m0 * wx0.w + m1 * wx1.w;
                    #pragma unroll
                    for (int off = 16; off; off >>= 1) {
                        p0 += __shfl_xor_sync(0xffffffffu, p0, off);
                        p1 += __shfl_xor_sync(0xffffffffu, p1, off);
                        p2 += __shfl_xor_sync(0xffffffffu, p2, off);
                        p3 += __shfl_xor_sync(0xffffffffu, p3, off);
                    }
                    if (lane == 0) {
                        S->wc[e * 4 + 0] = p0 + S->bxb[0];
                        S->wc[e * 4 + 1] = p1 + S->bxb[1];
                        S->wc[e * 4 + 2] = p2 + S->bxb[2];
                        S->wc[e * 4 + 3] = p3 + S->bxb[3];
                    }
                }
            }
            __syncthreads();

            // ---- phase 6: x update (tid<144) and u = silu([h,agg]@Wh1+bh1) (96 thr) ----
            if (tid < NA * 12) {
                int o = tid;
                int i = o / 12, dv = o - i * 12, v = dv & 3;
                float acc = 0.f;
                #pragma unroll
                for (int jj = 0; jj < 11; jj++) {
                    int e = i * 11 + jj;
                    acc += S->dif[e * 12 + dv] * S->wc[e * 4 + v];
                }
                float nx = S->x[o] + acc * (1.0f / 11.0f);
                S->x[o] = nx;
                if (!last) g_x[(size_t)env * NA * 12 + o] = nx;
            }
            if (!last && tid >= 256 && tid < 352) {
                int id = tid - 256;
                int node = id >> 3, kq = id & 7, k0 = kq * 8;
                float4 B0 = *(const float4*)&S->bh1v[k0];
                float4 B1 = *(const float4*)&S->bh1v[k0 + 4];
                float q0=B0.x,q1=B0.y,q2=B0.z,q3=B0.w,q4=B1.x,q5=B1.y,q6=B1.z,q7=B1.w;
                const float* hrow = &S->h[node * HST];
                const float* arow = &S->agg[node * HST];
                #pragma unroll 2
                for (int c4 = 0; c4 < HID; c4 += 4) {
                    float4 h4 = *(const float4*)&hrow[c4];
                    float4 a4 = *(const float4*)&arow[c4];
                    float hv[4] = {h4.x, h4.y, h4.z, h4.w};
                    float av[4] = {a4.x, a4.y, a4.z, a4.w};
                    #pragma unroll
                    for (int cc = 0; cc < 4; cc++) {
                        float4 w1a = *(const float4*)&S->Wh1w[(c4 + cc) * HID + k0];
                        float4 w1b = *(const float4*)&S->Wh1w[(c4 + cc) * HID + k0 + 4];
                        float4 w2a = *(const float4*)&S->Wh1w[(HID + c4 + cc) * HID + k0];
                        float4 w2b = *(const float4*)&S->Wh1w[(HID + c4 + cc) * HID + k0 + 4];
                        q0 += hv[cc] * w1a.x + av[cc] * w2a.x;
                        q1 += hv[cc] * w1a.y + av[cc] * w2a.y;
                        q2 += hv[cc] * w1a.z + av[cc] * w2a.z;
                        q3 += hv[cc] * w1a.w + av[cc] * w2a.w;
                        q4 += hv[cc] * w1b.x + av[cc] * w2b.x;
                        q5 += hv[cc] * w1b.y + av[cc] * w2b.y;
                        q6 += hv[cc] * w1b.z + av[cc] * w2b.z;
                        q7 += hv[cc] * w1b.w + av[cc] * w2b.w;
                    }
                }
                float* dst = &S->u[node * HST + k0];
                *(float4*)&dst[0] = make_float4(siluf(q0), siluf(q1), siluf(q2), siluf(q3));
                *(float4*)&dst[4] = make_float4(siluf(q4), siluf(q5), siluf(q6), siluf(q7));
            }
            __syncthreads();

            // ---- phase 7: h update + writeback (96 thr, 8 out), or final output ----
            if (!last) {
                if (tid < 96) {
                    int node = tid >> 3, kq = tid & 7, k0 = kq * 8;
                    float4 B0 = *(const float4*)&S->bh2v[k0];
                    float4 B1 = *(const float4*)&S->bh2v[k0 + 4];
                    float q0=B0.x,q1=B0.y,q2=B0.z,q3=B0.w,q4=B1.x,q5=B1.y,q6=B1.z,q7=B1.w;
                    const float* urow = &S->u[node * HST];
                    #pragma unroll 2
                    for (int c4 = 0; c4 < HID; c4 += 4) {
                        float4 u4 = *(const float4*)&urow[c4];
                        float uv[4] = {u4.x, u4.y, u4.z, u4.w};
                        #pragma unroll
                        for (int cc = 0; cc < 4; cc++) {
                            float4 w0 = *(const float4*)&S->Wh2w[(c4 + cc) * HID + k0];
                            float4 w1 = *(const float4*)&S->Wh2w[(c4 + cc) * HID + k0 + 4];
                            q0 += uv[cc] * w0.x; q1 += uv[cc] * w0.y; q2 += uv[cc] * w0.z; q3 += uv[cc] * w0.w;
                            q4 += uv[cc] * w1.x; q5 += uv[cc] * w1.y; q6 += uv[cc] * w1.z; q7 += uv[cc] * w1.w;
                        }
                    }
                    float4 hd0 = *(const float4*)&S->h[node * HST + k0];
                    float4 hd1 = *(const float4*)&S->h[node * HST + k0 + 4];
                    float* gdst = g_h + (size_t)env * NA * HID + node * HID + k0;
                    *(float4*)&gdst[0] = make_float4(hd0.x + q0, hd0.y + q1, hd0.z + q2, hd0.w + q3);
                    *(float4*)&gdst[4] = make_float4(hd1.x + q4, hd1.y + q5, hd1.z + q6, hd1.w + q7);
                }
            } else {
                if (tid < NA * DIM) {
                    int o = tid;
                    int i = o / 3, d = o - i * 3;
                    const float* xr = &S->x[i * 12 + d * 4];
                    float mu = xr[0] * wa0 + xr[1] * wa1 + xr[2] * wa2 + xr[3] * wa3;
                    out[(size_t)env * NA * DIM + o] = mu;
                    out[(size_t)NN * DIM + (size_t)env * NA * DIM + o] = lp[d];
                }
            }
            __syncthreads();
        }
        __syncthreads();
    }
}

extern "C" void kernel_launch(void* const* d_in, const int* in_sizes, int n_in,
                              void* d_out, int out_size) {
    (void)in_sizes; (void)n_in; (void)out_size;
    const float* h0      = (const float*)d_in[0];
    const float* x0      = (const float*)d_in[1];
    const float* W_embed = (const float*)d_in[2];
    const float* b_embed = (const float*)d_in[3];
    const float* We1     = (const float*)d_in[4];
    const float* be1     = (const float*)d_in[5];
    const float* We2     = (const float*)d_in[6];
    const float* be2     = (const float*)d_in[7];
    const float* Wx      = (const float*)d_in[8];
    const float* bx      = (const float*)d_in[9];
    const float* Wh1     = (const float*)d_in[10];
    const float* bh1     = (const float*)d_in[11];
    const float* Wh2     = (const float*)d_in[12];
    const float* bh2     = (const float*)d_in[13];
    const float* w_act   = (const float*)d_in[14];
    const float* log_std = (const float*)d_in[15];
    float* out = (float*)d_out;

    size_t smem = sizeof(Smem);
    cudaFuncSetAttribute(egnn_kernel, cudaFuncAttributeMaxDynamicSharedMemorySize, (int)smem);
    egnn_kernel<<<GRID, THREADS, smem>>>(h0, x0, W_embed, b_embed, We1, be1, We2, be2,
                                         Wx, bx, Wh1, bh1, Wh2, bh2, w_act, log_std, out);
}